// round 5
// baseline (speedup 1.0000x reference)
#include <cuda_runtime.h>
#include <cuda_bf16.h>
#include <math.h>

// Problem dims (fixed by the dataset)
#define BATCH   2
#define SEQ     2048
#define HID     1024
#define NHEAD   16
#define DH      64          // head dim
#define ROWS    (BATCH*SEQ) // 4096

// ---------------- scratch (no allocs allowed) ----------------
__device__ float g_qp[ROWS * HID];
__device__ float g_kp[ROWS * HID];
__device__ float g_vp[ROWS * HID];
__device__ float g_ctx[ROWS * HID];

// ---------------- GEMM: C[M,N] = A[M,K] @ B[K,N] + bias[N] ----------------
// 128x128 block tile, BK=8, 256 threads, 8x8 register microtile.
// Double-buffered shared memory: one __syncthreads per K-step, global loads
// for tile t+1 overlap the FMA block of tile t.
#define GBM 128
#define GBN 128
#define GBK 8

__global__ __launch_bounds__(256) void sgemm_bias_kernel(
    const float* __restrict__ A, const float* __restrict__ B,
    const float* __restrict__ bias, float* __restrict__ C,
    int M, int N, int K)
{
    __shared__ float As[2][GBK][GBM];
    __shared__ float Bs[2][GBK][GBN];

    const int tid = threadIdx.x;
    const int tr  = tid >> 4;        // 0..15
    const int tc  = tid & 15;        // 0..15
    const int row0 = blockIdx.y * GBM;
    const int col0 = blockIdx.x * GBN;

    const int arow = tid >> 1;        // 0..127
    const int acol = (tid & 1) * 4;   // 0 or 4
    const int brow = tid >> 5;        // 0..7
    const int bcol = (tid & 31) * 4;  // 0..124

    const float* Aptr = A + (size_t)(row0 + arow) * K + acol;
    const float* Bptr = B + (size_t)brow * N + col0 + bcol;

    float acc[8][8];
#pragma unroll
    for (int i = 0; i < 8; i++)
#pragma unroll
        for (int j = 0; j < 8; j++) acc[i][j] = 0.f;

    // ---- prologue: load tile 0 into buffer 0 ----
    {
        float4 a4 = *reinterpret_cast<const float4*>(Aptr);
        float4 b4 = *reinterpret_cast<const float4*>(Bptr);
        As[0][acol + 0][arow] = a4.x;
        As[0][acol + 1][arow] = a4.y;
        As[0][acol + 2][arow] = a4.z;
        As[0][acol + 3][arow] = a4.w;
        *reinterpret_cast<float4*>(&Bs[0][brow][bcol]) = b4;
    }
    __syncthreads();

    int cur = 0;
    for (int k0 = 0; k0 < K; k0 += GBK) {
        const int knext = k0 + GBK;
        float4 a4n, b4n;
        const bool has_next = (knext < K);
        if (has_next) {
            a4n = *reinterpret_cast<const float4*>(Aptr + knext);
            b4n = *reinterpret_cast<const float4*>(Bptr + (size_t)knext * N);
        }

#pragma unroll
        for (int kk = 0; kk < GBK; kk++) {
            float4 ar0 = *reinterpret_cast<const float4*>(&As[cur][kk][tr * 8]);
            float4 ar1 = *reinterpret_cast<const float4*>(&As[cur][kk][tr * 8 + 4]);
            float4 br0 = *reinterpret_cast<const float4*>(&Bs[cur][kk][tc * 8]);
            float4 br1 = *reinterpret_cast<const float4*>(&Bs[cur][kk][tc * 8 + 4]);
            float ar[8] = {ar0.x, ar0.y, ar0.z, ar0.w, ar1.x, ar1.y, ar1.z, ar1.w};
            float br[8] = {br0.x, br0.y, br0.z, br0.w, br1.x, br1.y, br1.z, br1.w};
#pragma unroll
            for (int i = 0; i < 8; i++)
#pragma unroll
                for (int j = 0; j < 8; j++)
                    acc[i][j] = fmaf(ar[i], br[j], acc[i][j]);
        }

        if (has_next) {
            const int nxt = cur ^ 1;
            As[nxt][acol + 0][arow] = a4n.x;
            As[nxt][acol + 1][arow] = a4n.y;
            As[nxt][acol + 2][arow] = a4n.z;
            As[nxt][acol + 3][arow] = a4n.w;
            *reinterpret_cast<float4*>(&Bs[nxt][brow][bcol]) = b4n;
            __syncthreads();
            cur = nxt;
        }
    }

    float bb[8];
#pragma unroll
    for (int j = 0; j < 8; j++) bb[j] = bias[col0 + tc * 8 + j];

#pragma unroll
    for (int i = 0; i < 8; i++) {
        const int row = row0 + tr * 8 + i;
        float* cp = C + (size_t)row * N + col0 + tc * 8;
        float4 o0, o1;
        o0.x = acc[i][0] + bb[0]; o0.y = acc[i][1] + bb[1];
        o0.z = acc[i][2] + bb[2]; o0.w = acc[i][3] + bb[3];
        o1.x = acc[i][4] + bb[4]; o1.y = acc[i][5] + bb[5];
        o1.z = acc[i][6] + bb[6]; o1.w = acc[i][7] + bb[7];
        *reinterpret_cast<float4*>(cp)     = o0;
        *reinterpret_cast<float4*>(cp + 4) = o1;
    }
}

// ---------------- flash attention (fp32) ----------------
// Block: (qtile=32 rows, head, batch). 128 threads.
// Each thread owns a 4x4 microtile of the 32x64 score tile / output tile.
#define TQ 32
#define TK 64
#define DHP (DH + 1)   // padded smem stride
#define TKP (TK + 1)

__global__ __launch_bounds__(128) void attn_kernel(
    const float* __restrict__ qp, const float* __restrict__ kp,
    const float* __restrict__ vp, const int* __restrict__ mask,
    float* __restrict__ ctx)
{
    extern __shared__ float sm[];
    float (*Qs)[DHP] = (float(*)[DHP])sm;                               // 32 x 65
    float (*Ks)[DHP] = (float(*)[DHP])(sm + TQ * DHP);                  // 64 x 65
    float (*Vs)[DHP] = (float(*)[DHP])(sm + TQ * DHP + TK * DHP);       // 64 x 65
    float (*Ps)[TKP] = (float(*)[TKP])(sm + TQ * DHP + 2 * TK * DHP);   // 32 x 65

    const int tid = threadIdx.x;
    const int qt = blockIdx.x, h = blockIdx.y, b = blockIdx.z;
    const int q0 = qt * TQ;
    const int tr = tid >> 4;   // 0..7  -> rows tr*4 .. tr*4+3
    const int tc = tid & 15;   // 0..15 -> cols tc*4 .. tc*4+3

    const float* qbase = qp + ((size_t)(b * SEQ + q0) * HID) + h * DH;
    const float* kbase = kp + ((size_t)b * SEQ) * HID + h * DH;
    const float* vbase = vp + ((size_t)b * SEQ) * HID + h * DH;
    const int*   mbase = mask + (size_t)(b * SEQ + q0) * SEQ;

    // load Q tile once
    for (int idx = tid; idx < TQ * DH; idx += 128) {
        const int r = idx >> 6, d = idx & 63;
        Qs[r][d] = qbase[(size_t)r * HID + d];
    }

    float m[4], l[4], acc[4][4];
#pragma unroll
    for (int i = 0; i < 4; i++) {
        m[i] = -1e30f; l[i] = 0.f;
#pragma unroll
        for (int j = 0; j < 4; j++) acc[i][j] = 0.f;
    }

    const float scale = 0.125f; // 1/sqrt(64)

    for (int kt = 0; kt < SEQ; kt += TK) {
        __syncthreads();  // protect Ks/Vs/Ps from previous iteration readers
        for (int idx = tid; idx < TK * DH; idx += 128) {
            const int r = idx >> 6, d = idx & 63;
            Ks[r][d] = kbase[(size_t)(kt + r) * HID + d];
            Vs[r][d] = vbase[(size_t)(kt + r) * HID + d];
        }
        __syncthreads();

        // scores: s[4][4] = Q[tr*4+i] . K[tc*4+j]
        float s[4][4];
#pragma unroll
        for (int i = 0; i < 4; i++)
#pragma unroll
            for (int j = 0; j < 4; j++) s[i][j] = 0.f;

#pragma unroll 8
        for (int kk = 0; kk < DH; kk++) {
            float ar[4], br[4];
#pragma unroll
            for (int i = 0; i < 4; i++) ar[i] = Qs[tr * 4 + i][kk];
#pragma unroll
            for (int j = 0; j < 4; j++) br[j] = Ks[tc * 4 + j][kk];
#pragma unroll
            for (int i = 0; i < 4; i++)
#pragma unroll
                for (int j = 0; j < 4; j++)
                    s[i][j] = fmaf(ar[i], br[j], s[i][j]);
        }

        // scale + mask + online softmax
#pragma unroll
        for (int i = 0; i < 4; i++) {
            const int4 mk = *reinterpret_cast<const int4*>(
                mbase + (size_t)(tr * 4 + i) * SEQ + kt + tc * 4);
            s[i][0] = mk.x ? s[i][0] * scale : -10000.f;
            s[i][1] = mk.y ? s[i][1] * scale : -10000.f;
            s[i][2] = mk.z ? s[i][2] * scale : -10000.f;
            s[i][3] = mk.w ? s[i][3] * scale : -10000.f;

            float mt = fmaxf(fmaxf(s[i][0], s[i][1]), fmaxf(s[i][2], s[i][3]));
#pragma unroll
            for (int off = 8; off; off >>= 1)
                mt = fmaxf(mt, __shfl_xor_sync(0xffffffffu, mt, off));
            const float mn = fmaxf(m[i], mt);
            const float alpha = __expf(m[i] - mn);
            m[i] = mn;

            float lt = 0.f;
#pragma unroll
            for (int j = 0; j < 4; j++) {
                s[i][j] = __expf(s[i][j] - mn);
                lt += s[i][j];
            }
#pragma unroll
            for (int off = 8; off; off >>= 1)
                lt += __shfl_xor_sync(0xffffffffu, lt, off);
            l[i] = l[i] * alpha + lt;
#pragma unroll
            for (int j = 0; j < 4; j++) acc[i][j] *= alpha;
#pragma unroll
            for (int j = 0; j < 4; j++) Ps[tr * 4 + i][tc * 4 + j] = s[i][j];
        }
        __syncthreads();

        // O += P @ V  (P: 32x64, V: 64x64 -> microtile rows tr*4+i, cols tc*4+j)
#pragma unroll 8
        for (int kk = 0; kk < TK; kk++) {
            float ar[4], br[4];
#pragma unroll
            for (int i = 0; i < 4; i++) ar[i] = Ps[tr * 4 + i][kk];
#pragma unroll
            for (int j = 0; j < 4; j++) br[j] = Vs[kk][tc * 4 + j];
#pragma unroll
            for (int i = 0; i < 4; i++)
#pragma unroll
                for (int j = 0; j < 4; j++)
                    acc[i][j] = fmaf(ar[i], br[j], acc[i][j]);
        }
    }

    // write: ctx[b, q, h*64 + d]
#pragma unroll
    for (int i = 0; i < 4; i++) {
        const float inv = 1.f / l[i];
        const int q = q0 + tr * 4 + i;
        float* o = ctx + ((size_t)(b * SEQ + q) * HID) + h * DH + tc * 4;
        float4 v;
        v.x = acc[i][0] * inv; v.y = acc[i][1] * inv;
        v.z = acc[i][2] * inv; v.w = acc[i][3] * inv;
        *reinterpret_cast<float4*>(o) = v;
    }
}

// ---------------- launch ----------------
extern "C" void kernel_launch(void* const* d_in, const int* in_sizes, int n_in,
                              void* d_out, int out_size)
{
    const float* q    = (const float*)d_in[0];
    const float* k    = (const float*)d_in[1];
    const float* v    = (const float*)d_in[2];
    const int*   mask = (const int*)  d_in[3];
    const float* w_q  = (const float*)d_in[4];
    const float* b_q  = (const float*)d_in[5];
    const float* w_k  = (const float*)d_in[6];
    const float* b_k  = (const float*)d_in[7];
    const float* w_v  = (const float*)d_in[8];
    const float* b_v  = (const float*)d_in[9];
    const float* w_o  = (const float*)d_in[10];
    const float* b_o  = (const float*)d_in[11];
    float* out = (float*)d_out;

    float *qp, *kp, *vp, *ctx;
    cudaGetSymbolAddress((void**)&qp,  g_qp);
    cudaGetSymbolAddress((void**)&kp,  g_kp);
    cudaGetSymbolAddress((void**)&vp,  g_vp);
    cudaGetSymbolAddress((void**)&ctx, g_ctx);

    const dim3 gemm_grid(HID / GBN, ROWS / GBM);  // (8, 32)
    sgemm_bias_kernel<<<gemm_grid, 256>>>(q, w_q, b_q, qp, ROWS, HID, HID);
    sgemm_bias_kernel<<<gemm_grid, 256>>>(k, w_k, b_k, kp, ROWS, HID, HID);
    sgemm_bias_kernel<<<gemm_grid, 256>>>(v, w_v, b_v, vp, ROWS, HID, HID);

    const int attn_smem = (TQ * DHP + 2 * TK * DHP + TQ * TKP) * (int)sizeof(float); // 49920 B
    cudaFuncSetAttribute(attn_kernel, cudaFuncAttributeMaxDynamicSharedMemorySize, attn_smem);
    attn_kernel<<<dim3(SEQ / TQ, NHEAD, BATCH), 128, attn_smem>>>(qp, kp, vp, mask, ctx);

    sgemm_bias_kernel<<<gemm_grid, 256>>>(ctx, w_o, b_o, out, ROWS, HID, HID);
}

// round 6
// speedup vs baseline: 1.0740x; 1.0740x over previous
#include <cuda_runtime.h>
#include <cuda_bf16.h>
#include <math.h>

// Problem dims (fixed by the dataset)
#define BATCH   2
#define SEQ     2048
#define HID     1024
#define NHEAD   16
#define DH      64          // head dim
#define ROWS    (BATCH*SEQ) // 4096

// ---------------- scratch (no allocs allowed) ----------------
__device__ float g_qp[ROWS * HID];
__device__ float g_kp[ROWS * HID];
__device__ float g_vp[ROWS * HID];
__device__ float g_ctx[ROWS * HID];

// ---------------- f32x2 packed helpers (sm_103a) ----------------
typedef unsigned long long u64f2;

__device__ __forceinline__ void fma2(u64f2 &d, u64f2 a, u64f2 b) {
    asm("fma.rn.f32x2 %0, %1, %2, %0;" : "+l"(d) : "l"(a), "l"(b));
}
__device__ __forceinline__ u64f2 pack2(float lo, float hi) {
    u64f2 r; asm("mov.b64 %0, {%1, %2};" : "=l"(r) : "f"(lo), "f"(hi)); return r;
}
__device__ __forceinline__ float2 unpack2(u64f2 v) {
    float2 r; asm("mov.b64 {%0, %1}, %2;" : "=f"(r.x), "=f"(r.y) : "l"(v)); return r;
}
__device__ __forceinline__ void mul2(u64f2 &d, u64f2 a) {
    asm("mul.rn.f32x2 %0, %0, %1;" : "+l"(d) : "l"(a));
}

// ---------------- GEMM: C[M,N] = A[M,K] @ B[K,N] + bias[N] ----------------
// 128x128 block tile, BK=8, 256 threads, 8x8 microtile, double-buffered smem.
// f32x2: accumulators paired over m (adjacent in As[k][m] layout -> LDS.64).
#define GBM 128
#define GBN 128
#define GBK 8

__global__ __launch_bounds__(256) void sgemm_bias_kernel(
    const float* __restrict__ A, const float* __restrict__ B,
    const float* __restrict__ bias, float* __restrict__ C,
    int M, int N, int K)
{
    __shared__ float As[2][GBK][GBM];
    __shared__ float Bs[2][GBK][GBN];

    const int tid = threadIdx.x;
    const int tr  = tid >> 4;        // 0..15
    const int tc  = tid & 15;        // 0..15
    const int row0 = blockIdx.y * GBM;
    const int col0 = blockIdx.x * GBN;

    const int arow = tid >> 1;        // 0..127
    const int acol = (tid & 1) * 4;   // 0 or 4
    const int brow = tid >> 5;        // 0..7
    const int bcol = (tid & 31) * 4;  // 0..124

    const float* Aptr = A + (size_t)(row0 + arow) * K + acol;
    const float* Bptr = B + (size_t)brow * N + col0 + bcol;

    // acc2[ip][j] packs rows (tr*8+2ip, tr*8+2ip+1) for column tc*8+j
    u64f2 acc2[4][8];
#pragma unroll
    for (int ip = 0; ip < 4; ip++)
#pragma unroll
        for (int j = 0; j < 8; j++) acc2[ip][j] = 0ull;

    // ---- prologue: load tile 0 into buffer 0 ----
    {
        float4 a4 = *reinterpret_cast<const float4*>(Aptr);
        float4 b4 = *reinterpret_cast<const float4*>(Bptr);
        As[0][acol + 0][arow] = a4.x;
        As[0][acol + 1][arow] = a4.y;
        As[0][acol + 2][arow] = a4.z;
        As[0][acol + 3][arow] = a4.w;
        *reinterpret_cast<float4*>(&Bs[0][brow][bcol]) = b4;
    }
    __syncthreads();

    int cur = 0;
    for (int k0 = 0; k0 < K; k0 += GBK) {
        const int knext = k0 + GBK;
        float4 a4n, b4n;
        const bool has_next = (knext < K);
        if (has_next) {
            a4n = *reinterpret_cast<const float4*>(Aptr + knext);
            b4n = *reinterpret_cast<const float4*>(Bptr + (size_t)knext * N);
        }

#pragma unroll
        for (int kk = 0; kk < GBK; kk++) {
            // a pairs: adjacent m in As[kk][*] -> direct LDS.64 (broadcast)
            u64f2 a2[4];
#pragma unroll
            for (int ip = 0; ip < 4; ip++)
                a2[ip] = *reinterpret_cast<const u64f2*>(&As[cur][kk][tr * 8 + 2 * ip]);
            // b scalars -> (b,b) packs
            float4 br0 = *reinterpret_cast<const float4*>(&Bs[cur][kk][tc * 8]);
            float4 br1 = *reinterpret_cast<const float4*>(&Bs[cur][kk][tc * 8 + 4]);
            float brr[8] = {br0.x, br0.y, br0.z, br0.w, br1.x, br1.y, br1.z, br1.w};
            u64f2 b2[8];
#pragma unroll
            for (int j = 0; j < 8; j++) b2[j] = pack2(brr[j], brr[j]);
#pragma unroll
            for (int ip = 0; ip < 4; ip++)
#pragma unroll
                for (int j = 0; j < 8; j++)
                    fma2(acc2[ip][j], a2[ip], b2[j]);
        }

        if (has_next) {
            const int nxt = cur ^ 1;
            As[nxt][acol + 0][arow] = a4n.x;
            As[nxt][acol + 1][arow] = a4n.y;
            As[nxt][acol + 2][arow] = a4n.z;
            As[nxt][acol + 3][arow] = a4n.w;
            *reinterpret_cast<float4*>(&Bs[nxt][brow][bcol]) = b4n;
            __syncthreads();
            cur = nxt;
        }
    }

    float bb[8];
#pragma unroll
    for (int j = 0; j < 8; j++) bb[j] = bias[col0 + tc * 8 + j];

#pragma unroll
    for (int ip = 0; ip < 4; ip++) {
        float r0[8], r1[8];
#pragma unroll
        for (int j = 0; j < 8; j++) {
            float2 v = unpack2(acc2[ip][j]);
            r0[j] = v.x + bb[j];
            r1[j] = v.y + bb[j];
        }
        const int row = row0 + tr * 8 + 2 * ip;
        float* cp0 = C + (size_t)row * N + col0 + tc * 8;
        float* cp1 = cp0 + N;
        *reinterpret_cast<float4*>(cp0)     = make_float4(r0[0], r0[1], r0[2], r0[3]);
        *reinterpret_cast<float4*>(cp0 + 4) = make_float4(r0[4], r0[5], r0[6], r0[7]);
        *reinterpret_cast<float4*>(cp1)     = make_float4(r1[0], r1[1], r1[2], r1[3]);
        *reinterpret_cast<float4*>(cp1 + 4) = make_float4(r1[4], r1[5], r1[6], r1[7]);
    }
}

// ---------------- flash attention v2 (fp32 + f32x2) ----------------
// Block: 64 q-rows, 64-k tiles, 128 threads (8x16), microtile 8(q) x 4(k).
// Qs/Vs/Ps plain row-major stride 64; Ks XOR-swizzled at float4 granularity.
#define ATQ 64
#define ATK 64

__global__ __launch_bounds__(128) void attn_kernel(
    const float* __restrict__ qp, const float* __restrict__ kp,
    const float* __restrict__ vp, const int* __restrict__ mask,
    float* __restrict__ ctx)
{
    extern __shared__ float sm[];
    float* Qs = sm;               // [64][64]
    float* Ks = sm + 4096;        // [64][64] swizzled
    float* Vs = sm + 8192;        // [64][64]
    float* Ps = sm + 12288;       // [64][64]

    const int tid = threadIdx.x;
    const int qt = blockIdx.x, h = blockIdx.y, b = blockIdx.z;
    const int q0 = qt * ATQ;
    const int tr = tid >> 4;   // 0..7  -> q-rows tr*8 .. tr*8+7
    const int tc = tid & 15;   // 0..15 -> k-cols tc*4 .. tc*4+3

    const float* qbase = qp + ((size_t)(b * SEQ + q0) * HID) + h * DH;
    const float* kbase = kp + ((size_t)b * SEQ) * HID + h * DH;
    const float* vbase = vp + ((size_t)b * SEQ) * HID + h * DH;
    const int*   mbase = mask + (size_t)(b * SEQ + q0) * SEQ;

    // load Q tile once (plain layout)
#pragma unroll
    for (int t = 0; t < 8; t++) {
        const int f = t * 128 + tid;
        const int r = f >> 4, c4 = f & 15;
        *reinterpret_cast<float4*>(&Qs[r * 64 + c4 * 4]) =
            *reinterpret_cast<const float4*>(&qbase[(size_t)r * HID + c4 * 4]);
    }

    float m[8], l[8];
    u64f2 acc2[8][4];
#pragma unroll
    for (int i = 0; i < 8; i++) {
        m[i] = -1e30f; l[i] = 0.f;
#pragma unroll
        for (int j = 0; j < 4; j++) acc2[i][j] = 0ull;
    }

    const float scale = 0.125f; // 1/sqrt(64)

    for (int kt = 0; kt < SEQ; kt += ATK) {
        __syncthreads();  // previous PV readers done with Ks/Vs/Ps
        // load K (swizzled) + V (plain)
#pragma unroll
        for (int t = 0; t < 8; t++) {
            const int f = t * 128 + tid;
            const int r = f >> 4, c4 = f & 15;
            float4 kv = *reinterpret_cast<const float4*>(&kbase[(size_t)(kt + r) * HID + c4 * 4]);
            float4 vv = *reinterpret_cast<const float4*>(&vbase[(size_t)(kt + r) * HID + c4 * 4]);
            const int slot = c4 ^ (r >> 2);
            *reinterpret_cast<float4*>(&Ks[r * 64 + slot * 4]) = kv;
            *reinterpret_cast<float4*>(&Vs[r * 64 + c4 * 4])   = vv;
        }
        __syncthreads();

        // ---- scores: s2[i][j] accumulates kk-pairs ----
        u64f2 s2[8][4];
#pragma unroll
        for (int i = 0; i < 8; i++)
#pragma unroll
            for (int j = 0; j < 4; j++) s2[i][j] = 0ull;

        {
            const float* qrow = Qs + (tr * 8) * 64;       // rows stride 64
            const float* krow = Ks + (tc * 4) * 64;
#pragma unroll 4
            for (int kk = 0; kk < ATK; kk += 2) {
                const int so = ((kk >> 2) ^ tc) * 4 + (kk & 3); // swizzled col offset (same for all 4 rows)
                u64f2 b2[4];
#pragma unroll
                for (int j = 0; j < 4; j++)
                    b2[j] = *reinterpret_cast<const u64f2*>(krow + j * 64 + so);
#pragma unroll
                for (int i = 0; i < 8; i++) {
                    const u64f2 a2 = *reinterpret_cast<const u64f2*>(qrow + i * 64 + kk);
#pragma unroll
                    for (int j = 0; j < 4; j++)
                        fma2(s2[i][j], a2, b2[j]);
                }
            }
        }

        // ---- scale + mask + online softmax, write P ----
#pragma unroll
        for (int i = 0; i < 8; i++) {
            float s[4];
#pragma unroll
            for (int j = 0; j < 4; j++) {
                float2 v = unpack2(s2[i][j]);
                s[j] = v.x + v.y;
            }
            const int4 mk = *reinterpret_cast<const int4*>(
                mbase + (size_t)(tr * 8 + i) * SEQ + kt + tc * 4);
            s[0] = mk.x ? s[0] * scale : -10000.f;
            s[1] = mk.y ? s[1] * scale : -10000.f;
            s[2] = mk.z ? s[2] * scale : -10000.f;
            s[3] = mk.w ? s[3] * scale : -10000.f;

            float mt = fmaxf(fmaxf(s[0], s[1]), fmaxf(s[2], s[3]));
#pragma unroll
            for (int off = 8; off; off >>= 1)
                mt = fmaxf(mt, __shfl_xor_sync(0xffffffffu, mt, off));
            const float mn = fmaxf(m[i], mt);
            const float alpha = __expf(m[i] - mn);
            m[i] = mn;

            float lt = 0.f;
#pragma unroll
            for (int j = 0; j < 4; j++) {
                s[j] = __expf(s[j] - mn);
                lt += s[j];
            }
#pragma unroll
            for (int off = 8; off; off >>= 1)
                lt += __shfl_xor_sync(0xffffffffu, lt, off);
            l[i] = l[i] * alpha + lt;

            const u64f2 al2 = pack2(alpha, alpha);
#pragma unroll
            for (int j = 0; j < 4; j++) mul2(acc2[i][j], al2);

            *reinterpret_cast<float4*>(&Ps[(tr * 8 + i) * 64 + tc * 4]) =
                make_float4(s[0], s[1], s[2], s[3]);
        }
        __syncthreads();

        // ---- O += P @ V (kk paired) ----
        {
            const float* prow = Ps + (tr * 8) * 64;
#pragma unroll 4
            for (int kk = 0; kk < ATK; kk += 2) {
                const float4 va = *reinterpret_cast<const float4*>(&Vs[kk * 64 + tc * 4]);
                const float4 vb = *reinterpret_cast<const float4*>(&Vs[(kk + 1) * 64 + tc * 4]);
                const u64f2 v2[4] = {
                    pack2(va.x, vb.x), pack2(va.y, vb.y),
                    pack2(va.z, vb.z), pack2(va.w, vb.w)
                };
#pragma unroll
                for (int i = 0; i < 8; i++) {
                    const u64f2 a2 = *reinterpret_cast<const u64f2*>(prow + i * 64 + kk);
#pragma unroll
                    for (int j = 0; j < 4; j++)
                        fma2(acc2[i][j], a2, v2[j]);
                }
            }
        }
    }

    // write: ctx[b, q, h*64 + d]
#pragma unroll
    for (int i = 0; i < 8; i++) {
        const float inv = 1.f / l[i];
        const int q = q0 + tr * 8 + i;
        float* o = ctx + ((size_t)(b * SEQ + q) * HID) + h * DH + tc * 4;
        float r[4];
#pragma unroll
        for (int j = 0; j < 4; j++) {
            float2 v = unpack2(acc2[i][j]);
            r[j] = (v.x + v.y) * inv;
        }
        *reinterpret_cast<float4*>(o) = make_float4(r[0], r[1], r[2], r[3]);
    }
}

// ---------------- launch ----------------
extern "C" void kernel_launch(void* const* d_in, const int* in_sizes, int n_in,
                              void* d_out, int out_size)
{
    const float* q    = (const float*)d_in[0];
    const float* k    = (const float*)d_in[1];
    const float* v    = (const float*)d_in[2];
    const int*   mask = (const int*)  d_in[3];
    const float* w_q  = (const float*)d_in[4];
    const float* b_q  = (const float*)d_in[5];
    const float* w_k  = (const float*)d_in[6];
    const float* b_k  = (const float*)d_in[7];
    const float* w_v  = (const float*)d_in[8];
    const float* b_v  = (const float*)d_in[9];
    const float* w_o  = (const float*)d_in[10];
    const float* b_o  = (const float*)d_in[11];
    float* out = (float*)d_out;

    float *qp, *kp, *vp, *ctx;
    cudaGetSymbolAddress((void**)&qp,  g_qp);
    cudaGetSymbolAddress((void**)&kp,  g_kp);
    cudaGetSymbolAddress((void**)&vp,  g_vp);
    cudaGetSymbolAddress((void**)&ctx, g_ctx);

    const dim3 gemm_grid(HID / GBN, ROWS / GBM);  // (8, 32)
    sgemm_bias_kernel<<<gemm_grid, 256>>>(q, w_q, b_q, qp, ROWS, HID, HID);
    sgemm_bias_kernel<<<gemm_grid, 256>>>(k, w_k, b_k, kp, ROWS, HID, HID);
    sgemm_bias_kernel<<<gemm_grid, 256>>>(v, w_v, b_v, vp, ROWS, HID, HID);

    const int attn_smem = 4 * 64 * 64 * (int)sizeof(float); // 65536 B
    cudaFuncSetAttribute(attn_kernel, cudaFuncAttributeMaxDynamicSharedMemorySize, attn_smem);
    attn_kernel<<<dim3(SEQ / ATQ, NHEAD, BATCH), 128, attn_smem>>>(qp, kp, vp, mask, ctx);

    sgemm_bias_kernel<<<gemm_grid, 256>>>(ctx, w_o, b_o, out, ROWS, HID, HID);
}